// round 3
// baseline (speedup 1.0000x reference)
#include <cuda_runtime.h>
#include <cstdint>

#define NN 100000
#define FDIM 128

// Scratch (device globals — allocation-free per harness rules)
__device__ float g_h[NN * FDIM];      // transformed features per layer
__device__ float g_out[NN * FDIM];    // unnormalized aggregated output
__device__ float g_asrc[NN * 4];
__device__ float g_adst[NN * 4];
__device__ float g_denom[NN * 4];
__device__ float g_wpad[FDIM * FDIM]; // Wc zero-padded to 128x128

// ---------------------------------------------------------------------------
// Tiled GEMM: C[M, out_cols] = act(A) @ W[128, 128-or-padded]
// A is [M,128]. Optional A-load transform: relu(a / (denom+1e-16) + bias_in).
// Optional output bias (bias_out). out_cols in {128, 40}.
// BM=64, BK=32, BN=128, 256 threads, thread tile 8x4.
// ---------------------------------------------------------------------------
__global__ void __launch_bounds__(256) gemm_k(
    const float* __restrict__ A, const float* __restrict__ W,
    float* __restrict__ C, int M, int out_cols,
    const float* __restrict__ denom, const float* __restrict__ bias_in,
    const float* __restrict__ bias_out)
{
    __shared__ float sA[64][36];   // padded stride (36 floats, 16B-aligned rows)
    __shared__ float sW[32][128];

    const int tid = threadIdx.x;
    const int tx = tid & 31;        // col group (4 cols each)
    const int ty = tid >> 5;        // row group (8 rows each)
    const int r0 = blockIdx.x * 64;

    float4 acc[8];
#pragma unroll
    for (int i = 0; i < 8; i++) acc[i] = make_float4(0.f, 0.f, 0.f, 0.f);

    for (int k0 = 0; k0 < 128; k0 += 32) {
        // ---- load A tile (64 x 32), 2 float4 per thread ----
#pragma unroll
        for (int i = 0; i < 2; i++) {
            int f = tid + i * 256;
            int row = f >> 3;
            int cg = f & 7;
            int grow = r0 + row;
            float4 v = make_float4(0.f, 0.f, 0.f, 0.f);
            if (grow < M) {
                v = *(const float4*)(A + (size_t)grow * 128 + k0 + cg * 4);
                if (denom) {
                    float dn = denom[grow * 4 + ((k0 + cg * 4) >> 5)] + 1e-16f;
                    float inv = 1.0f / dn;
                    float4 b = *(const float4*)(bias_in + k0 + cg * 4);
                    v.x = fmaxf(fmaf(v.x, inv, b.x), 0.f);
                    v.y = fmaxf(fmaf(v.y, inv, b.y), 0.f);
                    v.z = fmaxf(fmaf(v.z, inv, b.z), 0.f);
                    v.w = fmaxf(fmaf(v.w, inv, b.w), 0.f);
                }
            }
            *(float4*)&sA[row][cg * 4] = v;
        }
        // ---- load W tile (32 x 128), 4 float4 per thread ----
#pragma unroll
        for (int i = 0; i < 4; i++) {
            int f = tid + i * 256;
            int row = f >> 5;
            int cg = f & 31;
            *(float4*)&sW[row][cg * 4] =
                *(const float4*)(W + (size_t)(k0 + row) * 128 + cg * 4);
        }
        __syncthreads();

#pragma unroll 8
        for (int k = 0; k < 32; k++) {
            float4 w = *(float4*)&sW[k][tx * 4];
#pragma unroll
            for (int i = 0; i < 8; i++) {
                float a = sA[ty * 8 + i][k];
                acc[i].x = fmaf(a, w.x, acc[i].x);
                acc[i].y = fmaf(a, w.y, acc[i].y);
                acc[i].z = fmaf(a, w.z, acc[i].z);
                acc[i].w = fmaf(a, w.w, acc[i].w);
            }
        }
        __syncthreads();
    }

    int col = tx * 4;
    if (col < out_cols) {
        float4 bo = make_float4(0.f, 0.f, 0.f, 0.f);
        if (bias_out) bo = *(const float4*)(bias_out + col);
#pragma unroll
        for (int i = 0; i < 8; i++) {
            int grow = r0 + ty * 8 + i;
            if (grow < M) {
                float4 v = acc[i];
                v.x += bo.x; v.y += bo.y; v.z += bo.z; v.w += bo.w;
                *(float4*)(C + (size_t)grow * out_cols + col) = v;
            }
        }
    }
}

// ---------------------------------------------------------------------------
// Per-(node,head) attention logits: a_src[n,h] = h[n,h,:] . att_src[h,:]
// ---------------------------------------------------------------------------
__global__ void attn_k(const float* __restrict__ h,
                       const float* __restrict__ att_s,
                       const float* __restrict__ att_d,
                       float* __restrict__ a_s, float* __restrict__ a_d, int N4)
{
    int t = blockIdx.x * blockDim.x + threadIdx.x;
    if (t >= N4) return;
    int n = t >> 2, hh = t & 3;
    const float* hr = h + (size_t)n * 128 + hh * 32;
    const float* ws = att_s + hh * 32;
    const float* wd = att_d + hh * 32;
    float s1 = 0.f, s2 = 0.f;
#pragma unroll
    for (int c = 0; c < 32; c += 4) {
        float4 hv = *(const float4*)(hr + c);
        float4 w1 = *(const float4*)(ws + c);
        float4 w2 = *(const float4*)(wd + c);
        s1 += hv.x * w1.x + hv.y * w1.y + hv.z * w1.z + hv.w * w1.w;
        s2 += hv.x * w2.x + hv.y * w2.y + hv.z * w2.z + hv.w * w2.w;
    }
    a_s[t] = s1;
    a_d[t] = s2;
}

// ---------------------------------------------------------------------------
// Zero fill (float4 grid-stride)
// ---------------------------------------------------------------------------
__global__ void zero_k(float4* __restrict__ p, int n4)
{
    int i = blockIdx.x * blockDim.x + threadIdx.x;
    int stride = gridDim.x * blockDim.x;
    for (; i < n4; i += stride) p[i] = make_float4(0.f, 0.f, 0.f, 0.f);
}

// ---------------------------------------------------------------------------
// Pad Wc [128,40] into [128,128] with zeros
// ---------------------------------------------------------------------------
__global__ void pad_wc_k(const float* __restrict__ wc, float* __restrict__ wpad)
{
    int t = blockIdx.x * blockDim.x + threadIdx.x;
    if (t < 128 * 128) {
        int r = t >> 7, c = t & 127;
        wpad[t] = (c < 40) ? wc[r * 40 + c] : 0.f;
    }
}

// ---------------------------------------------------------------------------
// Edge scatter: one warp per edge (incl. self-loops).
//   p[h]   = exp(leaky_relu(a_src[s,h] + a_dst[d,h]))
//   out[d] += p[h] * h[s]   (vectorized fp32 reduction)
//   den[d] += p[h]          (lanes 0..3)
// ---------------------------------------------------------------------------
__global__ void __launch_bounds__(256) edge_k(
    const int* __restrict__ ei, int E, int N,
    const float* __restrict__ h,
    const float* __restrict__ a_s, const float* __restrict__ a_d,
    float* __restrict__ out, float* __restrict__ den)
{
    int w = (blockIdx.x * blockDim.x + threadIdx.x) >> 5;
    int lane = threadIdx.x & 31;
    int T = E + N;
    if (w >= T) return;

    int s, d;
    if (w < E) { s = __ldg(ei + w); d = __ldg(ei + E + w); }
    else       { s = w - E; d = s; }

    float4 as4 = *(const float4*)(a_s + 4 * (size_t)s);
    float4 ad4 = *(const float4*)(a_d + 4 * (size_t)d);

    // this lane's head = lane >> 3
    float es = (lane < 16) ? ((lane < 8) ? as4.x : as4.y)
                           : ((lane < 24) ? as4.z : as4.w);
    float ed = (lane < 16) ? ((lane < 8) ? ad4.x : ad4.y)
                           : ((lane < 24) ? ad4.z : ad4.w);
    float e = es + ed;
    e = (e > 0.f) ? e : 0.2f * e;
    float p = __expf(e);

    // lanes 0..3 accumulate the denominator for head=lane
    if (lane < 4) {
        float s2 = (lane == 0) ? as4.x : (lane == 1) ? as4.y : (lane == 2) ? as4.z : as4.w;
        float d2 = (lane == 0) ? ad4.x : (lane == 1) ? ad4.y : (lane == 2) ? ad4.z : ad4.w;
        float ee = s2 + d2;
        ee = (ee > 0.f) ? ee : 0.2f * ee;
        atomicAdd(den + 4 * (size_t)d + lane, __expf(ee));
    }

    float4 hv = *(const float4*)(h + (size_t)s * 128 + lane * 4);
    float* dst = out + (size_t)d * 128 + lane * 4;
    asm volatile("red.global.add.v4.f32 [%0], {%1, %2, %3, %4};"
                 :: "l"(dst), "f"(p * hv.x), "f"(p * hv.y),
                    "f"(p * hv.z), "f"(p * hv.w)
                 : "memory");
}

// ---------------------------------------------------------------------------
extern "C" void kernel_launch(void* const* d_in, const int* in_sizes, int n_in,
                              void* d_out, int out_size)
{
    const float* x   = (const float*)d_in[0];
    const int*   ei  = (const int*)  d_in[1];
    const float* W1  = (const float*)d_in[2];
    const float* as1 = (const float*)d_in[3];
    const float* ad1 = (const float*)d_in[4];
    const float* b1  = (const float*)d_in[5];
    const float* W2  = (const float*)d_in[6];
    const float* as2 = (const float*)d_in[7];
    const float* ad2 = (const float*)d_in[8];
    const float* b2  = (const float*)d_in[9];
    const float* Wc  = (const float*)d_in[10];
    const float* bc  = (const float*)d_in[11];
    float* out = (float*)d_out;

    const int N = in_sizes[0] / 128;
    const int E = in_sizes[1] / 2;

    float *hbuf, *obuf, *asb, *adb, *den, *wpad;
    cudaGetSymbolAddress((void**)&hbuf, g_h);
    cudaGetSymbolAddress((void**)&obuf, g_out);
    cudaGetSymbolAddress((void**)&asb,  g_asrc);
    cudaGetSymbolAddress((void**)&adb,  g_adst);
    cudaGetSymbolAddress((void**)&den,  g_denom);
    cudaGetSymbolAddress((void**)&wpad, g_wpad);

    const dim3 gGemm((N + 63) / 64);
    const int  gAttn = (N * 4 + 255) / 256;
    const int  T = E + N;                      // edges + self-loops
    const int  gEdge = (T + 7) / 8;            // 8 warps/block

    // prep: padded classifier weights (independent of the rest)
    pad_wc_k<<<(128 * 128 + 255) / 256, 256>>>(Wc, wpad);

    // ---- layer 1 ----
    gemm_k<<<gGemm, 256>>>(x, W1, hbuf, N, 128, nullptr, nullptr, nullptr);
    attn_k<<<gAttn, 256>>>(hbuf, as1, ad1, asb, adb, N * 4);
    zero_k<<<1024, 256>>>((float4*)obuf, N * 128 / 4);
    zero_k<<<256, 256>>>((float4*)den, N * 4 / 4);
    edge_k<<<gEdge, 256>>>(ei, E, N, hbuf, asb, adb, obuf, den);

    // ---- layer 2 (A-load: relu(out1/den + b1)) ----
    gemm_k<<<gGemm, 256>>>(obuf, W2, hbuf, N, 128, den, b1, nullptr);
    attn_k<<<gAttn, 256>>>(hbuf, as2, ad2, asb, adb, N * 4);
    zero_k<<<1024, 256>>>((float4*)obuf, N * 128 / 4);
    zero_k<<<256, 256>>>((float4*)den, N * 4 / 4);
    edge_k<<<gEdge, 256>>>(ei, E, N, hbuf, asb, adb, obuf, den);

    // ---- classifier (A-load: relu(out2/den + b2)), +bc, 40 cols ----
    gemm_k<<<gGemm, 256>>>(obuf, wpad, out, N, 40, den, b2, bc);
}

// round 4
// speedup vs baseline: 2.1763x; 2.1763x over previous
#include <cuda_runtime.h>
#include <cstdint>

#define NN 100000
#define FDIM 128
#define EMAX 1700032           // capacity for E + N (1.6M + 100k)
#define NBMAX 512              // blocks for scan (ceil(100000/256)=391)

typedef unsigned long long ull;

// Scratch (device globals — allocation-free per harness rules)
__device__ float g_h[NN * FDIM];      // transformed features per layer
__device__ float g_out[NN * FDIM];    // normalized aggregated output
__device__ float g_asrc[NN * 4];
__device__ float g_adst[NN * 4];
__device__ float g_wpad[FDIM * FDIM]; // Wc zero-padded to 128x128
__device__ int   g_rowptr[NN + 1];
__device__ int   g_wcur[NN];          // counts, then write cursors
__device__ int   g_csrc[EMAX];        // CSR src indices grouped by dst
__device__ int   g_bsum[NBMAX];       // per-block sums for scan

// ---------------------------------------------------------------------------
// packed f32x2 helpers (sm_103a FFMA2 path — ptxas never auto-emits this)
// ---------------------------------------------------------------------------
#define PACK2(out, lo, hi) \
    asm("mov.b64 %0, {%1, %2};" : "=l"(out) : "f"(lo), "f"(hi))
#define UNPK2(lo, hi, in) \
    asm("mov.b64 {%0, %1}, %2;" : "=f"(lo), "=f"(hi) : "l"(in))
#define FMA2(d, a, b, c) \
    asm("fma.rn.f32x2 %0, %1, %2, %3;" : "=l"(d) : "l"(a), "l"(b), "l"(c))

// ---------------------------------------------------------------------------
// Tiled GEMM with packed f32x2 FMA: C[M, out_cols] = act(A) @ W[128, 128pad]
// Optional A-load transform: relu(a + bias_in). Optional output bias.
// BM=64, BK=32, BN=128, 256 threads; thread tile 8 rows (4 pairs) x 4 cols.
// A tile stored TRANSPOSED (sAT[k][row]) so row pairs load as LDS.64,
// broadcast across the warp (ty constant within a warp).
// ---------------------------------------------------------------------------
__global__ void __launch_bounds__(256) gemm_k(
    const float* __restrict__ A, const float* __restrict__ W,
    float* __restrict__ C, int M, int out_cols,
    const float* __restrict__ bias_in, const float* __restrict__ bias_out)
{
    __shared__ float sAT[32][66];  // [k][row], stride 66 keeps 8B align + low conflict
    __shared__ float sW[32][128];

    const int tid = threadIdx.x;
    const int tx = tid & 31;        // col group (4 cols each)
    const int ty = tid >> 5;        // row group (8 rows each) — constant per warp
    const int r0 = blockIdx.x * 64;

    ull acc[4][4];
#pragma unroll
    for (int p = 0; p < 4; p++)
#pragma unroll
        for (int c = 0; c < 4; c++) acc[p][c] = 0ull;

    for (int k0 = 0; k0 < 128; k0 += 32) {
        // ---- load A tile (64 rows x 32 k) transposed, 2 float4 per thread ----
#pragma unroll
        for (int i = 0; i < 2; i++) {
            int f = tid + i * 256;
            int row = f >> 3;       // 0..63
            int cg = f & 7;         // 0..7 (k group of 4)
            int grow = r0 + row;
            float4 v = make_float4(0.f, 0.f, 0.f, 0.f);
            if (grow < M) {
                v = *(const float4*)(A + (size_t)grow * 128 + k0 + cg * 4);
                if (bias_in) {
                    float4 b = *(const float4*)(bias_in + k0 + cg * 4);
                    v.x = fmaxf(v.x + b.x, 0.f);
                    v.y = fmaxf(v.y + b.y, 0.f);
                    v.z = fmaxf(v.z + b.z, 0.f);
                    v.w = fmaxf(v.w + b.w, 0.f);
                }
            }
            sAT[cg * 4 + 0][row] = v.x;
            sAT[cg * 4 + 1][row] = v.y;
            sAT[cg * 4 + 2][row] = v.z;
            sAT[cg * 4 + 3][row] = v.w;
        }
        // ---- load W tile (32 x 128), 4 float4 per thread ----
#pragma unroll
        for (int i = 0; i < 4; i++) {
            int f = tid + i * 256;
            int row = f >> 5;
            int cg = f & 31;
            *(float4*)&sW[row][cg * 4] =
                *(const float4*)(W + (size_t)(k0 + row) * 128 + cg * 4);
        }
        __syncthreads();

#pragma unroll 8
        for (int k = 0; k < 32; k++) {
            float4 w = *(float4*)&sW[k][tx * 4];
            ull b0, b1, b2, b3;
            PACK2(b0, w.x, w.x);
            PACK2(b1, w.y, w.y);
            PACK2(b2, w.z, w.z);
            PACK2(b3, w.w, w.w);
            const ull* ap = (const ull*)&sAT[k][ty * 8];  // broadcast in warp
            ull a0 = ap[0], a1 = ap[1], a2 = ap[2], a3 = ap[3];
            FMA2(acc[0][0], a0, b0, acc[0][0]);
            FMA2(acc[0][1], a0, b1, acc[0][1]);
            FMA2(acc[0][2], a0, b2, acc[0][2]);
            FMA2(acc[0][3], a0, b3, acc[0][3]);
            FMA2(acc[1][0], a1, b0, acc[1][0]);
            FMA2(acc[1][1], a1, b1, acc[1][1]);
            FMA2(acc[1][2], a1, b2, acc[1][2]);
            FMA2(acc[1][3], a1, b3, acc[1][3]);
            FMA2(acc[2][0], a2, b0, acc[2][0]);
            FMA2(acc[2][1], a2, b1, acc[2][1]);
            FMA2(acc[2][2], a2, b2, acc[2][2]);
            FMA2(acc[2][3], a2, b3, acc[2][3]);
            FMA2(acc[3][0], a3, b0, acc[3][0]);
            FMA2(acc[3][1], a3, b1, acc[3][1]);
            FMA2(acc[3][2], a3, b2, acc[3][2]);
            FMA2(acc[3][3], a3, b3, acc[3][3]);
        }
        __syncthreads();
    }

    int col = tx * 4;
    if (col < out_cols) {
        float4 bo = make_float4(0.f, 0.f, 0.f, 0.f);
        if (bias_out) bo = *(const float4*)(bias_out + col);
#pragma unroll
        for (int p = 0; p < 4; p++) {
            float4 v0, v1;
            UNPK2(v0.x, v1.x, acc[p][0]);
            UNPK2(v0.y, v1.y, acc[p][1]);
            UNPK2(v0.z, v1.z, acc[p][2]);
            UNPK2(v0.w, v1.w, acc[p][3]);
            int gr0 = r0 + ty * 8 + 2 * p;
            if (gr0 < M) {
                v0.x += bo.x; v0.y += bo.y; v0.z += bo.z; v0.w += bo.w;
                *(float4*)(C + (size_t)gr0 * out_cols + col) = v0;
            }
            if (gr0 + 1 < M) {
                v1.x += bo.x; v1.y += bo.y; v1.z += bo.z; v1.w += bo.w;
                *(float4*)(C + (size_t)(gr0 + 1) * out_cols + col) = v1;
            }
        }
    }
}

// ---------------------------------------------------------------------------
// Per-(node,head) attention logits
// ---------------------------------------------------------------------------
__global__ void attn_k(const float* __restrict__ h,
                       const float* __restrict__ att_s,
                       const float* __restrict__ att_d,
                       float* __restrict__ a_s, float* __restrict__ a_d, int N4)
{
    int t = blockIdx.x * blockDim.x + threadIdx.x;
    if (t >= N4) return;
    int n = t >> 2, hh = t & 3;
    const float* hr = h + (size_t)n * 128 + hh * 32;
    const float* ws = att_s + hh * 32;
    const float* wd = att_d + hh * 32;
    float s1 = 0.f, s2 = 0.f;
#pragma unroll
    for (int c = 0; c < 32; c += 4) {
        float4 hv = *(const float4*)(hr + c);
        float4 w1 = *(const float4*)(ws + c);
        float4 w2 = *(const float4*)(wd + c);
        s1 += hv.x * w1.x + hv.y * w1.y + hv.z * w1.z + hv.w * w1.w;
        s2 += hv.x * w2.x + hv.y * w2.y + hv.z * w2.z + hv.w * w2.w;
    }
    a_s[t] = s1;
    a_d[t] = s2;
}

// ---------------------------------------------------------------------------
// Pad Wc [128,40] into [128,128] with zeros
// ---------------------------------------------------------------------------
__global__ void pad_wc_k(const float* __restrict__ wc, float* __restrict__ wpad)
{
    int t = blockIdx.x * blockDim.x + threadIdx.x;
    if (t < 128 * 128) {
        int r = t >> 7, c = t & 127;
        wpad[t] = (c < 40) ? wc[r * 40 + c] : 0.f;
    }
}

// ---------------------------------------------------------------------------
// CSR build: counts (self-loop seeded), 3-kernel scan, scatter fill
// ---------------------------------------------------------------------------
__global__ void init_cnt_k(int* __restrict__ cnt, int N)
{
    int i = blockIdx.x * blockDim.x + threadIdx.x;
    if (i < N) cnt[i] = 1;   // self-loop
}

__global__ void count_k(const int* __restrict__ ei, int E, int* __restrict__ cnt)
{
    int i = blockIdx.x * blockDim.x + threadIdx.x;
    if (i < E) atomicAdd(cnt + __ldg(ei + E + i), 1);
}

__global__ void blocksum_k(const int* __restrict__ cnt, int* __restrict__ bsum, int N)
{
    __shared__ int s[256];
    int i = blockIdx.x * 256 + threadIdx.x;
    s[threadIdx.x] = (i < N) ? cnt[i] : 0;
    __syncthreads();
#pragma unroll
    for (int st = 128; st > 0; st >>= 1) {
        if (threadIdx.x < st) s[threadIdx.x] += s[threadIdx.x + st];
        __syncthreads();
    }
    if (threadIdx.x == 0) bsum[blockIdx.x] = s[0];
}

__global__ void scan_bsums_k(int* __restrict__ bsum, int NB)
{
    __shared__ int s[NBMAX];
    int t = threadIdx.x;
    int x = (t < NB) ? bsum[t] : 0;
    s[t] = x;
    __syncthreads();
#pragma unroll
    for (int off = 1; off < NBMAX; off <<= 1) {
        int v = (t >= off) ? s[t - off] : 0;
        __syncthreads();
        s[t] += v;
        __syncthreads();
    }
    bsum[t < NBMAX ? t : 0] = s[t] - x;  // exclusive
}

__global__ void scan_final_k(const int* __restrict__ cnt,
                             const int* __restrict__ boff,
                             int* __restrict__ rowptr,
                             int* __restrict__ wcur, int N)
{
    __shared__ int s[256];
    int t = threadIdx.x;
    int i = blockIdx.x * 256 + t;
    int x = (i < N) ? cnt[i] : 0;
    s[t] = x;
    __syncthreads();
#pragma unroll
    for (int off = 1; off < 256; off <<= 1) {
        int v = (t >= off) ? s[t - off] : 0;
        __syncthreads();
        s[t] += v;
        __syncthreads();
    }
    int excl = s[t] - x + boff[blockIdx.x];
    if (i < N) {
        rowptr[i] = excl;
        wcur[i] = excl;
        if (i == N - 1) rowptr[N] = excl + x;
    }
}

__global__ void fill_k(const int* __restrict__ ei, int E, int N,
                       int* __restrict__ wcur, int* __restrict__ csrc)
{
    int t = blockIdx.x * blockDim.x + threadIdx.x;
    int T = E + N;
    if (t >= T) return;
    int s, d;
    if (t < E) { s = __ldg(ei + t); d = __ldg(ei + E + t); }
    else       { s = t - E; d = s; }
    int pos = atomicAdd(wcur + d, 1);
    csrc[pos] = s;
}

// ---------------------------------------------------------------------------
// Aggregation: one warp per dst node — gather h[src], softmax-normalize,
// write normalized output once. No atomics.
// ---------------------------------------------------------------------------
__global__ void __launch_bounds__(256) agg_k(
    const int* __restrict__ rowptr, const int* __restrict__ csrc,
    const float* __restrict__ h,
    const float* __restrict__ a_s, const float* __restrict__ a_d,
    float* __restrict__ out, int N)
{
    int d = (blockIdx.x * blockDim.x + threadIdx.x) >> 5;
    int lane = threadIdx.x & 31;
    if (d >= N) return;

    int beg = __ldg(rowptr + d);
    int end = __ldg(rowptr + d + 1);
    int head = lane >> 3;
    float ed = __ldg(a_d + 4 * (size_t)d + head);

    float4 acc = make_float4(0.f, 0.f, 0.f, 0.f);
    float den = 0.f;

    for (int e = beg; e < end; e++) {
        int s = __ldg(csrc + e);
        float es = __ldg(a_s + 4 * (size_t)s + head);
        float t = es + ed;
        t = (t > 0.f) ? t : 0.2f * t;
        float p = __expf(t);
        float4 hv = *(const float4*)(h + (size_t)s * 128 + lane * 4);
        acc.x = fmaf(p, hv.x, acc.x);
        acc.y = fmaf(p, hv.y, acc.y);
        acc.z = fmaf(p, hv.z, acc.z);
        acc.w = fmaf(p, hv.w, acc.w);
        den += p;
    }
    float inv = 1.0f / (den + 1e-16f);
    acc.x *= inv; acc.y *= inv; acc.z *= inv; acc.w *= inv;
    *(float4*)(out + (size_t)d * 128 + lane * 4) = acc;
}

// ---------------------------------------------------------------------------
extern "C" void kernel_launch(void* const* d_in, const int* in_sizes, int n_in,
                              void* d_out, int out_size)
{
    const float* x   = (const float*)d_in[0];
    const int*   ei  = (const int*)  d_in[1];
    const float* W1  = (const float*)d_in[2];
    const float* as1 = (const float*)d_in[3];
    const float* ad1 = (const float*)d_in[4];
    const float* b1  = (const float*)d_in[5];
    const float* W2  = (const float*)d_in[6];
    const float* as2 = (const float*)d_in[7];
    const float* ad2 = (const float*)d_in[8];
    const float* b2  = (const float*)d_in[9];
    const float* Wc  = (const float*)d_in[10];
    const float* bc  = (const float*)d_in[11];
    float* out = (float*)d_out;

    const int N = in_sizes[0] / 128;
    const int E = in_sizes[1] / 2;

    float *hbuf, *obuf, *asb, *adb, *wpad;
    int *rowptr, *wcur, *csrc, *bsum;
    cudaGetSymbolAddress((void**)&hbuf,   g_h);
    cudaGetSymbolAddress((void**)&obuf,   g_out);
    cudaGetSymbolAddress((void**)&asb,    g_asrc);
    cudaGetSymbolAddress((void**)&adb,    g_adst);
    cudaGetSymbolAddress((void**)&wpad,   g_wpad);
    cudaGetSymbolAddress((void**)&rowptr, g_rowptr);
    cudaGetSymbolAddress((void**)&wcur,   g_wcur);
    cudaGetSymbolAddress((void**)&csrc,   g_csrc);
    cudaGetSymbolAddress((void**)&bsum,   g_bsum);

    const dim3 gGemm((N + 63) / 64);
    const int  gAttn = (N * 4 + 255) / 256;
    const int  NB = (N + 255) / 256;
    const int  T = E + N;
    const int  gAgg = (N + 7) / 8;   // warp per node, 8 warps/block

    // ---- CSR build (graph shared by both layers) ----
    pad_wc_k<<<(128 * 128 + 255) / 256, 256>>>(Wc, wpad);
    init_cnt_k<<<NB, 256>>>(wcur, N);
    count_k<<<(E + 255) / 256, 256>>>(ei, E, wcur);
    blocksum_k<<<NB, 256>>>(wcur, bsum, N);
    scan_bsums_k<<<1, NBMAX>>>(bsum, NB);
    scan_final_k<<<NB, 256>>>(wcur, bsum, rowptr, wcur, N);
    fill_k<<<(T + 255) / 256, 256>>>(ei, E, N, wcur, csrc);

    // ---- layer 1 ----
    gemm_k<<<gGemm, 256>>>(x, W1, hbuf, N, 128, nullptr, nullptr);
    attn_k<<<gAttn, 256>>>(hbuf, as1, ad1, asb, adb, N * 4);
    agg_k<<<gAgg, 256>>>(rowptr, csrc, hbuf, asb, adb, obuf, N);

    // ---- layer 2 (A-load: relu(a + b1)) ----
    gemm_k<<<gGemm, 256>>>(obuf, W2, hbuf, N, 128, b1, nullptr);
    attn_k<<<gAttn, 256>>>(hbuf, as2, ad2, asb, adb, N * 4);
    agg_k<<<gAgg, 256>>>(rowptr, csrc, hbuf, asb, adb, obuf, N);

    // ---- classifier (A-load: relu(a + b2)), +bc, 40 cols ----
    gemm_k<<<gGemm, 256>>>(obuf, wpad, out, N, 40, b2, bc);
}

// round 5
// speedup vs baseline: 2.6845x; 1.2335x over previous
#include <cuda_runtime.h>
#include <cuda_fp16.h>
#include <cstdint>

#define NN 100000
#define FDIM 128
#define EMAX 1700032           // capacity for E + N (1.6M + 100k)
#define NBMAX 512              // blocks for scan (ceil(100000/256)=391)

typedef unsigned long long ull;

// Scratch (device globals — allocation-free per harness rules)
__device__ __half g_h16[NN * FDIM];   // fp16 transformed features (messages)
__device__ float g_out[NN * FDIM];    // normalized aggregated output
__device__ float g_asrc[NN * 4];
__device__ float g_adst[NN * 4];
__device__ float g_wpad[FDIM * 64];   // Wc zero-padded to 128x64
__device__ int   g_rowptr[NN + 1];
__device__ int   g_wcur[NN];          // counts, then write cursors
__device__ int   g_csrc[EMAX];        // CSR src indices grouped by dst
__device__ int   g_bsum[NBMAX];       // per-block sums for scan

// ---------------------------------------------------------------------------
// packed f32x2 helpers (sm_103a FFMA2 path — ptxas never auto-emits this)
// ---------------------------------------------------------------------------
#define PACK2(out, lo, hi) \
    asm("mov.b64 %0, {%1, %2};" : "=l"(out) : "f"(lo), "f"(hi))
#define UNPK2(lo, hi, in) \
    asm("mov.b64 {%0, %1}, %2;" : "=f"(lo), "=f"(hi) : "l"(in))
#define FMA2(d, a, b, c) \
    asm("fma.rn.f32x2 %0, %1, %2, %3;" : "=l"(d) : "l"(a), "l"(b), "l"(c))

// ---------------------------------------------------------------------------
// Layer GEMM, fully fused: h = act(A) @ W  (act = relu(a+bias_in) if bias_in)
//   writes h as fp16 (message table) and a_src/a_dst per (node,head) via
//   in-register dot + shfl reduction — no fp32 h, no separate attn kernel.
// BM=64, BK=32, BN=128, 256 threads; thread tile 8 rows (4 f32x2 pairs) x 4 cols.
// ---------------------------------------------------------------------------
__global__ void __launch_bounds__(256) gemm_h_k(
    const float* __restrict__ A, const float* __restrict__ W,
    __half* __restrict__ h16,
    float* __restrict__ a_s, float* __restrict__ a_d,
    const float* __restrict__ att_s, const float* __restrict__ att_d,
    const float* __restrict__ bias_in, int M)
{
    __shared__ float sAT[32][66];  // [k][row]
    __shared__ float sW[32][128];

    const int tid = threadIdx.x;
    const int tx = tid & 31;        // col group (4 cols each)
    const int ty = tid >> 5;        // row group (8 rows) — constant per warp
    const int r0 = blockIdx.x * 64;

    ull acc[4][4];
#pragma unroll
    for (int p = 0; p < 4; p++)
#pragma unroll
        for (int c = 0; c < 4; c++) acc[p][c] = 0ull;

    for (int k0 = 0; k0 < 128; k0 += 32) {
#pragma unroll
        for (int i = 0; i < 2; i++) {
            int f = tid + i * 256;
            int row = f >> 3;
            int cg = f & 7;
            int grow = r0 + row;
            float4 v = make_float4(0.f, 0.f, 0.f, 0.f);
            if (grow < M) {
                v = *(const float4*)(A + (size_t)grow * 128 + k0 + cg * 4);
                if (bias_in) {
                    float4 b = *(const float4*)(bias_in + k0 + cg * 4);
                    v.x = fmaxf(v.x + b.x, 0.f);
                    v.y = fmaxf(v.y + b.y, 0.f);
                    v.z = fmaxf(v.z + b.z, 0.f);
                    v.w = fmaxf(v.w + b.w, 0.f);
                }
            }
            sAT[cg * 4 + 0][row] = v.x;
            sAT[cg * 4 + 1][row] = v.y;
            sAT[cg * 4 + 2][row] = v.z;
            sAT[cg * 4 + 3][row] = v.w;
        }
#pragma unroll
        for (int i = 0; i < 4; i++) {
            int f = tid + i * 256;
            int row = f >> 5;
            int cg = f & 31;
            *(float4*)&sW[row][cg * 4] =
                *(const float4*)(W + (size_t)(k0 + row) * 128 + cg * 4);
        }
        __syncthreads();

#pragma unroll 8
        for (int k = 0; k < 32; k++) {
            float4 w = *(float4*)&sW[k][tx * 4];
            ull b0, b1, b2, b3;
            PACK2(b0, w.x, w.x);
            PACK2(b1, w.y, w.y);
            PACK2(b2, w.z, w.z);
            PACK2(b3, w.w, w.w);
            const ull* ap = (const ull*)&sAT[k][ty * 8];
            ull a0 = ap[0], a1 = ap[1], a2 = ap[2], a3 = ap[3];
            FMA2(acc[0][0], a0, b0, acc[0][0]);
            FMA2(acc[0][1], a0, b1, acc[0][1]);
            FMA2(acc[0][2], a0, b2, acc[0][2]);
            FMA2(acc[0][3], a0, b3, acc[0][3]);
            FMA2(acc[1][0], a1, b0, acc[1][0]);
            FMA2(acc[1][1], a1, b1, acc[1][1]);
            FMA2(acc[1][2], a1, b2, acc[1][2]);
            FMA2(acc[1][3], a1, b3, acc[1][3]);
            FMA2(acc[2][0], a2, b0, acc[2][0]);
            FMA2(acc[2][1], a2, b1, acc[2][1]);
            FMA2(acc[2][2], a2, b2, acc[2][2]);
            FMA2(acc[2][3], a2, b3, acc[2][3]);
            FMA2(acc[3][0], a3, b0, acc[3][0]);
            FMA2(acc[3][1], a3, b1, acc[3][1]);
            FMA2(acc[3][2], a3, b2, acc[3][2]);
            FMA2(acc[3][3], a3, b3, acc[3][3]);
        }
        __syncthreads();
    }

    // ---- fused epilogue: fp16 h store + attention logits ----
    const int col = tx * 4;
    const int head = tx >> 3;
    const int cl = (tx & 7) * 4;  // col within head
    float4 ws = *(const float4*)(att_s + head * 32 + cl);
    float4 wd = *(const float4*)(att_d + head * 32 + cl);

#pragma unroll
    for (int p = 0; p < 4; p++) {
        float4 v0, v1;
        UNPK2(v0.x, v1.x, acc[p][0]);
        UNPK2(v0.y, v1.y, acc[p][1]);
        UNPK2(v0.z, v1.z, acc[p][2]);
        UNPK2(v0.w, v1.w, acc[p][3]);
        int gr0 = r0 + ty * 8 + 2 * p;
        int gr1 = gr0 + 1;

        if (gr0 < M) {
            __half2 ha = __floats2half2_rn(v0.x, v0.y);
            __half2 hb = __floats2half2_rn(v0.z, v0.w);
            uint2 pk = make_uint2(*(unsigned*)&ha, *(unsigned*)&hb);
            *(uint2*)(h16 + (size_t)gr0 * 128 + col) = pk;
        }
        if (gr1 < M) {
            __half2 ha = __floats2half2_rn(v1.x, v1.y);
            __half2 hb = __floats2half2_rn(v1.z, v1.w);
            uint2 pk = make_uint2(*(unsigned*)&ha, *(unsigned*)&hb);
            *(uint2*)(h16 + (size_t)gr1 * 128 + col) = pk;
        }

        float ps0 = v0.x * ws.x + v0.y * ws.y + v0.z * ws.z + v0.w * ws.w;
        float pd0 = v0.x * wd.x + v0.y * wd.y + v0.z * wd.z + v0.w * wd.w;
        float ps1 = v1.x * ws.x + v1.y * ws.y + v1.z * ws.z + v1.w * ws.w;
        float pd1 = v1.x * wd.x + v1.y * wd.y + v1.z * wd.z + v1.w * wd.w;
#pragma unroll
        for (int off = 4; off > 0; off >>= 1) {
            ps0 += __shfl_xor_sync(0xFFFFFFFF, ps0, off);
            pd0 += __shfl_xor_sync(0xFFFFFFFF, pd0, off);
            ps1 += __shfl_xor_sync(0xFFFFFFFF, ps1, off);
            pd1 += __shfl_xor_sync(0xFFFFFFFF, pd1, off);
        }
        if ((tx & 7) == 0) {
            if (gr0 < M) {
                a_s[(size_t)gr0 * 4 + head] = ps0;
                a_d[(size_t)gr0 * 4 + head] = pd0;
            }
            if (gr1 < M) {
                a_s[(size_t)gr1 * 4 + head] = ps1;
                a_d[(size_t)gr1 * 4 + head] = pd1;
            }
        }
    }
}

// ---------------------------------------------------------------------------
// Classifier GEMM: C[M,40] = relu(A + bias_in) @ Wpad[128,64], + bias_out.
// BM=128, BN=64, 256 threads; thread tile 8 rows x 4 cols (tx 0..15).
// ---------------------------------------------------------------------------
__global__ void __launch_bounds__(256) gemm_cls_k(
    const float* __restrict__ A, const float* __restrict__ W,
    float* __restrict__ C,
    const float* __restrict__ bias_in, const float* __restrict__ bias_out,
    int M)
{
    __shared__ float sAT[32][130];  // [k][row], BM=128
    __shared__ float sW[32][64];

    const int tid = threadIdx.x;
    const int tx = tid & 15;        // 16 col groups x 4 = 64 cols
    const int ty = tid >> 4;        // 16 row groups x 8 = 128 rows
    const int r0 = blockIdx.x * 128;

    ull acc[4][4];
#pragma unroll
    for (int p = 0; p < 4; p++)
#pragma unroll
        for (int c = 0; c < 4; c++) acc[p][c] = 0ull;

    for (int k0 = 0; k0 < 128; k0 += 32) {
#pragma unroll
        for (int i = 0; i < 4; i++) {
            int f = tid + i * 256;
            int row = f >> 3;       // 0..127
            int cg = f & 7;
            int grow = r0 + row;
            float4 v = make_float4(0.f, 0.f, 0.f, 0.f);
            if (grow < M) {
                v = *(const float4*)(A + (size_t)grow * 128 + k0 + cg * 4);
                float4 b = *(const float4*)(bias_in + k0 + cg * 4);
                v.x = fmaxf(v.x + b.x, 0.f);
                v.y = fmaxf(v.y + b.y, 0.f);
                v.z = fmaxf(v.z + b.z, 0.f);
                v.w = fmaxf(v.w + b.w, 0.f);
            }
            sAT[cg * 4 + 0][row] = v.x;
            sAT[cg * 4 + 1][row] = v.y;
            sAT[cg * 4 + 2][row] = v.z;
            sAT[cg * 4 + 3][row] = v.w;
        }
#pragma unroll
        for (int i = 0; i < 2; i++) {
            int f = tid + i * 256;
            int row = f >> 4;
            int cg = f & 15;
            *(float4*)&sW[row][cg * 4] =
                *(const float4*)(W + (size_t)(k0 + row) * 64 + cg * 4);
        }
        __syncthreads();

#pragma unroll 8
        for (int k = 0; k < 32; k++) {
            float4 w = *(float4*)&sW[k][tx * 4];
            ull b0, b1, b2, b3;
            PACK2(b0, w.x, w.x);
            PACK2(b1, w.y, w.y);
            PACK2(b2, w.z, w.z);
            PACK2(b3, w.w, w.w);
            const ull* ap = (const ull*)&sAT[k][ty * 8];
            ull a0 = ap[0], a1 = ap[1], a2 = ap[2], a3 = ap[3];
            FMA2(acc[0][0], a0, b0, acc[0][0]);
            FMA2(acc[0][1], a0, b1, acc[0][1]);
            FMA2(acc[0][2], a0, b2, acc[0][2]);
            FMA2(acc[0][3], a0, b3, acc[0][3]);
            FMA2(acc[1][0], a1, b0, acc[1][0]);
            FMA2(acc[1][1], a1, b1, acc[1][1]);
            FMA2(acc[1][2], a1, b2, acc[1][2]);
            FMA2(acc[1][3], a1, b3, acc[1][3]);
            FMA2(acc[2][0], a2, b0, acc[2][0]);
            FMA2(acc[2][1], a2, b1, acc[2][1]);
            FMA2(acc[2][2], a2, b2, acc[2][2]);
            FMA2(acc[2][3], a2, b3, acc[2][3]);
            FMA2(acc[3][0], a3, b0, acc[3][0]);
            FMA2(acc[3][1], a3, b1, acc[3][1]);
            FMA2(acc[3][2], a3, b2, acc[3][2]);
            FMA2(acc[3][3], a3, b3, acc[3][3]);
        }
        __syncthreads();
    }

    int col = tx * 4;
    if (col < 40) {
        float4 bo = *(const float4*)(bias_out + col);
#pragma unroll
        for (int p = 0; p < 4; p++) {
            float4 v0, v1;
            UNPK2(v0.x, v1.x, acc[p][0]);
            UNPK2(v0.y, v1.y, acc[p][1]);
            UNPK2(v0.z, v1.z, acc[p][2]);
            UNPK2(v0.w, v1.w, acc[p][3]);
            int gr0 = r0 + ty * 8 + 2 * p;
            if (gr0 < M) {
                v0.x += bo.x; v0.y += bo.y; v0.z += bo.z; v0.w += bo.w;
                *(float4*)(C + (size_t)gr0 * 40 + col) = v0;
            }
            if (gr0 + 1 < M) {
                v1.x += bo.x; v1.y += bo.y; v1.z += bo.z; v1.w += bo.w;
                *(float4*)(C + (size_t)(gr0 + 1) * 40 + col) = v1;
            }
        }
    }
}

// ---------------------------------------------------------------------------
// Pad Wc [128,40] into [128,64] with zeros
// ---------------------------------------------------------------------------
__global__ void pad_wc_k(const float* __restrict__ wc, float* __restrict__ wpad)
{
    int t = blockIdx.x * blockDim.x + threadIdx.x;
    if (t < 128 * 64) {
        int r = t >> 6, c = t & 63;
        wpad[t] = (c < 40) ? wc[r * 40 + c] : 0.f;
    }
}

// ---------------------------------------------------------------------------
// CSR build: counts (self-loop seeded), 3-kernel scan, scatter fill
// ---------------------------------------------------------------------------
__global__ void init_cnt_k(int* __restrict__ cnt, int N)
{
    int i = blockIdx.x * blockDim.x + threadIdx.x;
    if (i < N) cnt[i] = 1;   // self-loop
}

__global__ void count_k(const int* __restrict__ ei, int E, int* __restrict__ cnt)
{
    int i = blockIdx.x * blockDim.x + threadIdx.x;
    if (i < E) atomicAdd(cnt + __ldg(ei + E + i), 1);
}

__global__ void blocksum_k(const int* __restrict__ cnt, int* __restrict__ bsum, int N)
{
    __shared__ int s[256];
    int i = blockIdx.x * 256 + threadIdx.x;
    s[threadIdx.x] = (i < N) ? cnt[i] : 0;
    __syncthreads();
#pragma unroll
    for (int st = 128; st > 0; st >>= 1) {
        if (threadIdx.x < st) s[threadIdx.x] += s[threadIdx.x + st];
        __syncthreads();
    }
    if (threadIdx.x == 0) bsum[blockIdx.x] = s[0];
}

__global__ void scan_bsums_k(int* __restrict__ bsum, int NB)
{
    __shared__ int s[NBMAX];
    int t = threadIdx.x;
    int x = (t < NB) ? bsum[t] : 0;
    s[t] = x;
    __syncthreads();
#pragma unroll
    for (int off = 1; off < NBMAX; off <<= 1) {
        int v = (t >= off) ? s[t - off] : 0;
        __syncthreads();
        s[t] += v;
        __syncthreads();
    }
    bsum[t < NBMAX ? t : 0] = s[t] - x;  // exclusive
}

__global__ void scan_final_k(const int* __restrict__ cnt,
                             const int* __restrict__ boff,
                             int* __restrict__ rowptr,
                             int* __restrict__ wcur, int N)
{
    __shared__ int s[256];
    int t = threadIdx.x;
    int i = blockIdx.x * 256 + t;
    int x = (i < N) ? cnt[i] : 0;
    s[t] = x;
    __syncthreads();
#pragma unroll
    for (int off = 1; off < 256; off <<= 1) {
        int v = (t >= off) ? s[t - off] : 0;
        __syncthreads();
        s[t] += v;
        __syncthreads();
    }
    int excl = s[t] - x + boff[blockIdx.x];
    if (i < N) {
        rowptr[i] = excl;
        wcur[i] = excl;
        if (i == N - 1) rowptr[N] = excl + x;
    }
}

__global__ void fill_k(const int* __restrict__ ei, int E, int N,
                       int* __restrict__ wcur, int* __restrict__ csrc)
{
    int t = blockIdx.x * blockDim.x + threadIdx.x;
    int T = E + N;
    if (t >= T) return;
    int s, d;
    if (t < E) { s = __ldg(ei + t); d = __ldg(ei + E + t); }
    else       { s = t - E; d = s; }
    int pos = atomicAdd(wcur + d, 1);
    csrc[pos] = s;
}

// ---------------------------------------------------------------------------
// Aggregation: one warp per dst node — gather fp16 h[src], softmax-normalize
// in fp32, write normalized fp32 output once. No atomics.
// ---------------------------------------------------------------------------
__global__ void __launch_bounds__(256) agg_k(
    const int* __restrict__ rowptr, const int* __restrict__ csrc,
    const __half* __restrict__ h16,
    const float* __restrict__ a_s, const float* __restrict__ a_d,
    float* __restrict__ out, int N)
{
    int d = (blockIdx.x * blockDim.x + threadIdx.x) >> 5;
    int lane = threadIdx.x & 31;
    if (d >= N) return;

    int beg = __ldg(rowptr + d);
    int end = __ldg(rowptr + d + 1);
    int head = lane >> 3;
    float ed = __ldg(a_d + 4 * (size_t)d + head);

    float4 acc = make_float4(0.f, 0.f, 0.f, 0.f);
    float den = 0.f;

    for (int e = beg; e < end; e++) {
        int s = __ldg(csrc + e);
        float es = __ldg(a_s + 4 * (size_t)s + head);
        float t = es + ed;
        t = (t > 0.f) ? t : 0.2f * t;
        float p = __expf(t);
        uint2 pk = *(const uint2*)(h16 + (size_t)s * 128 + lane * 4);
        float2 f0 = __half22float2(*(__half2*)&pk.x);
        float2 f1 = __half22float2(*(__half2*)&pk.y);
        acc.x = fmaf(p, f0.x, acc.x);
        acc.y = fmaf(p, f0.y, acc.y);
        acc.z = fmaf(p, f1.x, acc.z);
        acc.w = fmaf(p, f1.y, acc.w);
        den += p;
    }
    float inv = 1.0f / (den + 1e-16f);
    acc.x *= inv; acc.y *= inv; acc.z *= inv; acc.w *= inv;
    *(float4*)(out + (size_t)d * 128 + lane * 4) = acc;
}

// ---------------------------------------------------------------------------
extern "C" void kernel_launch(void* const* d_in, const int* in_sizes, int n_in,
                              void* d_out, int out_size)
{
    const float* x   = (const float*)d_in[0];
    const int*   ei  = (const int*)  d_in[1];
    const float* W1  = (const float*)d_in[2];
    const float* as1 = (const float*)d_in[3];
    const float* ad1 = (const float*)d_in[4];
    const float* b1  = (const float*)d_in[5];
    const float* W2  = (const float*)d_in[6];
    const float* as2 = (const float*)d_in[7];
    const float* ad2 = (const float*)d_in[8];
    const float* b2  = (const float*)d_in[9];
    const float* Wc  = (const float*)d_in[10];
    const float* bc  = (const float*)d_in[11];
    float* out = (float*)d_out;

    const int N = in_sizes[0] / 128;
    const int E = in_sizes[1] / 2;

    __half* h16;
    float *obuf, *asb, *adb, *wpad;
    int *rowptr, *wcur, *csrc, *bsum;
    cudaGetSymbolAddress((void**)&h16,    g_h16);
    cudaGetSymbolAddress((void**)&obuf,   g_out);
    cudaGetSymbolAddress((void**)&asb,    g_asrc);
    cudaGetSymbolAddress((void**)&adb,    g_adst);
    cudaGetSymbolAddress((void**)&wpad,   g_wpad);
    cudaGetSymbolAddress((void**)&rowptr, g_rowptr);
    cudaGetSymbolAddress((void**)&wcur,   g_wcur);
    cudaGetSymbolAddress((void**)&csrc,   g_csrc);
    cudaGetSymbolAddress((void**)&bsum,   g_bsum);

    const dim3 gGemm((N + 63) / 64);
    const dim3 gCls((N + 127) / 128);
    const int  NB = (N + 255) / 256;
    const int  T = E + N;
    const int  gAgg = (N + 7) / 8;   // warp per node, 8 warps/block

    // ---- CSR build (graph shared by both layers) ----
    pad_wc_k<<<(128 * 64 + 255) / 256, 256>>>(Wc, wpad);
    init_cnt_k<<<NB, 256>>>(wcur, N);
    count_k<<<(E + 255) / 256, 256>>>(ei, E, wcur);
    blocksum_k<<<NB, 256>>>(wcur, bsum, N);
    scan_bsums_k<<<1, NBMAX>>>(bsum, NB);
    scan_final_k<<<NB, 256>>>(wcur, bsum, rowptr, wcur, N);
    fill_k<<<(T + 255) / 256, 256>>>(ei, E, N, wcur, csrc);

    // ---- layer 1 (gemm + fused attn + fp16 h) ----
    gemm_h_k<<<gGemm, 256>>>(x, W1, h16, asb, adb, as1, ad1, nullptr, N);
    agg_k<<<gAgg, 256>>>(rowptr, csrc, h16, asb, adb, obuf, N);

    // ---- layer 2 (A-load: relu(a + b1)) ----
    gemm_h_k<<<gGemm, 256>>>(obuf, W2, h16, asb, adb, as2, ad2, b1, N);
    agg_k<<<gAgg, 256>>>(rowptr, csrc, h16, asb, adb, obuf, N);

    // ---- classifier (A-load: relu(a + b2)), +bc, 40 real cols ----
    gemm_cls_k<<<gCls, 256>>>(obuf, wpad, out, b2, bc, N);
}

// round 7
// speedup vs baseline: 2.8093x; 1.0465x over previous
#include <cuda_runtime.h>
#include <cuda_fp16.h>
#include <cstdint>

#define NN 100000
#define FDIM 128
#define EMAX 1700032
#define NBMAX 512

typedef unsigned long long ull;

// Scratch (device globals — allocation-free per harness rules)
__device__ __half g_h16[NN * FDIM];   // fp16 transformed features (messages)
__device__ float g_out[NN * FDIM];    // normalized aggregated output (fp32)
__device__ float g_asrc[NN * 4];
__device__ float g_adst[NN * 4];
__device__ float g_wpad[FDIM * 64];   // Wc zero-padded to 128x64
__device__ int   g_rowptr[NN + 1];
__device__ int   g_wcur[NN];
__device__ int   g_csrc[EMAX];
__device__ int   g_bsum[NBMAX];

// ---------------------------------------------------------------------------
// packed f32x2 helpers (classifier GEMM)
// ---------------------------------------------------------------------------
#define PACK2(out, lo, hi) \
    asm("mov.b64 %0, {%1, %2};" : "=l"(out) : "f"(lo), "f"(hi))
#define UNPK2(lo, hi, in) \
    asm("mov.b64 {%0, %1}, %2;" : "=f"(lo), "=f"(hi) : "l"(in))
#define FMA2(d, a, b, c) \
    asm("fma.rn.f32x2 %0, %1, %2, %3;" : "=l"(d) : "l"(a), "l"(b), "l"(c))

// tf32 helpers (legacy mma.sync path — compiles for plain sm_103)
__device__ __forceinline__ uint32_t f2tf(float f) {
    uint32_t r;
    asm("cvt.rna.tf32.f32 %0, %1;" : "=r"(r) : "f"(f));
    return r;
}
#define MMA_TF32(c, a, b) \
    asm volatile("mma.sync.aligned.m16n8k8.row.col.f32.tf32.tf32.f32 " \
        "{%0,%1,%2,%3}, {%4,%5,%6,%7}, {%8,%9}, {%0,%1,%2,%3};" \
        : "+f"((c)[0]), "+f"((c)[1]), "+f"((c)[2]), "+f"((c)[3]) \
        : "r"((a)[0]), "r"((a)[1]), "r"((a)[2]), "r"((a)[3]), \
          "r"((b)[0]), "r"((b)[1]))

// ---------------------------------------------------------------------------
// TF32 tensor-core layer GEMM: h16[M,128] = act(A[M,128]) @ W[128,128]  (fp16 out)
// act = relu(a + bias_in) when bias_in != nullptr.
// BM=128, BN=128, BK=32, 256 threads (8 warps: 4 along M x 2 along N).
// Each warp: 32x64 output = 2 (m16) x 8 (n8) mma tiles, fp32 accum.
// ---------------------------------------------------------------------------
__global__ void __launch_bounds__(256) mma_gemm_k(
    const float* __restrict__ A, const float* __restrict__ Wg,
    __half* __restrict__ h16, const float* __restrict__ bias_in, int M)
{
    __shared__ uint32_t sA[128][36];   // [row][k], stride 36: conflict-free frags
    __shared__ uint32_t sW[32][132];   // [k][n],  stride 132: conflict-free frags

    const int tid = threadIdx.x;
    const int lane = tid & 31;
    const int w = tid >> 5;
    const int wm = (w & 3) * 32;       // warp row base
    const int wn = (w >> 2) * 64;      // warp col base
    const int r0 = blockIdx.x * 128;

    float acc[2][8][4];
#pragma unroll
    for (int tm = 0; tm < 2; tm++)
#pragma unroll
        for (int tn = 0; tn < 8; tn++)
#pragma unroll
            for (int i = 0; i < 4; i++) acc[tm][tn][i] = 0.f;

    for (int kb = 0; kb < 4; kb++) {
        // ---- A tile (128 x 32), fused act, cvt tf32 ----
#pragma unroll
        for (int i = 0; i < 4; i++) {
            int idx = tid + i * 256;           // 1024 float4
            int row = idx >> 3;
            int cg = idx & 7;
            int gr = r0 + row;
            float4 v = make_float4(0.f, 0.f, 0.f, 0.f);
            if (gr < M) {
                v = *(const float4*)(A + (size_t)gr * 128 + kb * 32 + cg * 4);
                if (bias_in) {
                    float4 b = *(const float4*)(bias_in + kb * 32 + cg * 4);
                    v.x = fmaxf(v.x + b.x, 0.f);
                    v.y = fmaxf(v.y + b.y, 0.f);
                    v.z = fmaxf(v.z + b.z, 0.f);
                    v.w = fmaxf(v.w + b.w, 0.f);
                }
            }
            uint4 t = make_uint4(f2tf(v.x), f2tf(v.y), f2tf(v.z), f2tf(v.w));
            *(uint4*)&sA[row][cg * 4] = t;
        }
        // ---- W tile (32 x 128), cvt tf32 ----
#pragma unroll
        for (int i = 0; i < 4; i++) {
            int idx = tid + i * 256;
            int k = idx >> 5;
            int ng = idx & 31;
            float4 v = *(const float4*)(Wg + (size_t)(kb * 32 + k) * 128 + ng * 4);
            uint4 t = make_uint4(f2tf(v.x), f2tf(v.y), f2tf(v.z), f2tf(v.w));
            *(uint4*)&sW[k][ng * 4] = t;
        }
        __syncthreads();

#pragma unroll
        for (int k8 = 0; k8 < 4; k8++) {
            const int kq = k8 * 8 + (lane & 3);
            const int rb = wm + (lane >> 2);
            const int nb = wn + (lane >> 2);
            uint32_t a[2][4], b[8][2];
#pragma unroll
            for (int tm = 0; tm < 2; tm++) {
                a[tm][0] = sA[rb + tm * 16 + 0][kq];
                a[tm][1] = sA[rb + tm * 16 + 8][kq];
                a[tm][2] = sA[rb + tm * 16 + 0][kq + 4];
                a[tm][3] = sA[rb + tm * 16 + 8][kq + 4];
            }
#pragma unroll
            for (int tn = 0; tn < 8; tn++) {
                b[tn][0] = sW[kq + 0][nb + tn * 8];
                b[tn][1] = sW[kq + 4][nb + tn * 8];
            }
#pragma unroll
            for (int tm = 0; tm < 2; tm++)
#pragma unroll
                for (int tn = 0; tn < 8; tn++)
                    MMA_TF32(acc[tm][tn], a[tm], b[tn]);
        }
        __syncthreads();
    }

    // ---- epilogue: fp16 store. c0,c1 = cols (lane&3)*2, +1 (adjacent!) ----
#pragma unroll
    for (int tm = 0; tm < 2; tm++)
#pragma unroll
        for (int h2 = 0; h2 < 2; h2++) {
            int gr = r0 + wm + tm * 16 + (lane >> 2) + 8 * h2;
            if (gr < M) {
#pragma unroll
                for (int tn = 0; tn < 8; tn++) {
                    __half2 hh = __floats2half2_rn(acc[tm][tn][2 * h2],
                                                   acc[tm][tn][2 * h2 + 1]);
                    *(uint32_t*)(h16 + (size_t)gr * 128 + wn + tn * 8 +
                                 (lane & 3) * 2) = *(uint32_t*)&hh;
                }
            }
        }
}

// ---------------------------------------------------------------------------
// Attention logits from fp16 h: a_src[n,h] = h[n,h,:] . att_src[h,:]
// ---------------------------------------------------------------------------
__global__ void attn16_k(const __half* __restrict__ h,
                         const float* __restrict__ att_s,
                         const float* __restrict__ att_d,
                         float* __restrict__ a_s, float* __restrict__ a_d, int N4)
{
    int t = blockIdx.x * blockDim.x + threadIdx.x;
    if (t >= N4) return;
    int n = t >> 2, hh = t & 3;
    const __half* hr = h + (size_t)n * 128 + hh * 32;
    const float* ws = att_s + hh * 32;
    const float* wd = att_d + hh * 32;
    float s1 = 0.f, s2 = 0.f;
#pragma unroll
    for (int c = 0; c < 32; c += 4) {
        uint2 pk = *(const uint2*)(hr + c);
        float2 f0 = __half22float2(*(__half2*)&pk.x);
        float2 f1 = __half22float2(*(__half2*)&pk.y);
        float4 w1 = *(const float4*)(ws + c);
        float4 w2 = *(const float4*)(wd + c);
        s1 += f0.x * w1.x + f0.y * w1.y + f1.x * w1.z + f1.y * w1.w;
        s2 += f0.x * w2.x + f0.y * w2.y + f1.x * w2.z + f1.y * w2.w;
    }
    a_s[t] = s1;
    a_d[t] = s2;
}

// ---------------------------------------------------------------------------
// Classifier GEMM (exact fp32 FFMA2): C[M,40] = relu(A + b_in) @ Wpad[128,64] + b_out
// ---------------------------------------------------------------------------
__global__ void __launch_bounds__(256) gemm_cls_k(
    const float* __restrict__ A, const float* __restrict__ W,
    float* __restrict__ C,
    const float* __restrict__ bias_in, const float* __restrict__ bias_out,
    int M)
{
    __shared__ float sAT[32][130];
    __shared__ float sW[32][64];

    const int tid = threadIdx.x;
    const int tx = tid & 15;
    const int ty = tid >> 4;
    const int r0 = blockIdx.x * 128;

    ull acc[4][4];
#pragma unroll
    for (int p = 0; p < 4; p++)
#pragma unroll
        for (int c = 0; c < 4; c++) acc[p][c] = 0ull;

    for (int k0 = 0; k0 < 128; k0 += 32) {
#pragma unroll
        for (int i = 0; i < 4; i++) {
            int f = tid + i * 256;
            int row = f >> 3;
            int cg = f & 7;
            int grow = r0 + row;
            float4 v = make_float4(0.f, 0.f, 0.f, 0.f);
            if (grow < M) {
                v = *(const float4*)(A + (size_t)grow * 128 + k0 + cg * 4);
                float4 b = *(const float4*)(bias_in + k0 + cg * 4);
                v.x = fmaxf(v.x + b.x, 0.f);
                v.y = fmaxf(v.y + b.y, 0.f);
                v.z = fmaxf(v.z + b.z, 0.f);
                v.w = fmaxf(v.w + b.w, 0.f);
            }
            sAT[cg * 4 + 0][row] = v.x;
            sAT[cg * 4 + 1][row] = v.y;
            sAT[cg * 4 + 2][row] = v.z;
            sAT[cg * 4 + 3][row] = v.w;
        }
#pragma unroll
        for (int i = 0; i < 2; i++) {
            int f = tid + i * 256;
            int row = f >> 4;
            int cg = f & 15;
            *(float4*)&sW[row][cg * 4] =
                *(const float4*)(W + (size_t)(k0 + row) * 64 + cg * 4);
        }
        __syncthreads();

#pragma unroll 8
        for (int k = 0; k < 32; k++) {
            float4 w = *(float4*)&sW[k][tx * 4];
            ull b0, b1, b2, b3;
            PACK2(b0, w.x, w.x);
            PACK2(b1, w.y, w.y);
            PACK2(b2, w.z, w.z);
            PACK2(b3, w.w, w.w);
            const ull* ap = (const ull*)&sAT[k][ty * 8];
            ull a0 = ap[0], a1 = ap[1], a2 = ap[2], a3 = ap[3];
            FMA2(acc[0][0], a0, b0, acc[0][0]);
            FMA2(acc[0][1], a0, b1, acc[0][1]);
            FMA2(acc[0][2], a0, b2, acc[0][2]);
            FMA2(acc[0][3], a0, b3, acc[0][3]);
            FMA2(acc[1][0], a1, b0, acc[1][0]);
            FMA2(acc[1][1], a1, b1, acc[1][1]);
            FMA2(acc[1][2], a1, b2, acc[1][2]);
            FMA2(acc[1][3], a1, b3, acc[1][3]);
            FMA2(acc[2][0], a2, b0, acc[2][0]);
            FMA2(acc[2][1], a2, b1, acc[2][1]);
            FMA2(acc[2][2], a2, b2, acc[2][2]);
            FMA2(acc[2][3], a2, b3, acc[2][3]);
            FMA2(acc[3][0], a3, b0, acc[3][0]);
            FMA2(acc[3][1], a3, b1, acc[3][1]);
            FMA2(acc[3][2], a3, b2, acc[3][2]);
            FMA2(acc[3][3], a3, b3, acc[3][3]);
        }
        __syncthreads();
    }

    int col = tx * 4;
    if (col < 40) {
        float4 bo = *(const float4*)(bias_out + col);
#pragma unroll
        for (int p = 0; p < 4; p++) {
            float4 v0, v1;
            UNPK2(v0.x, v1.x, acc[p][0]);
            UNPK2(v0.y, v1.y, acc[p][1]);
            UNPK2(v0.z, v1.z, acc[p][2]);
            UNPK2(v0.w, v1.w, acc[p][3]);
            int gr0 = r0 + ty * 8 + 2 * p;
            if (gr0 < M) {
                v0.x += bo.x; v0.y += bo.y; v0.z += bo.z; v0.w += bo.w;
                *(float4*)(C + (size_t)gr0 * 40 + col) = v0;
            }
            if (gr0 + 1 < M) {
                v1.x += bo.x; v1.y += bo.y; v1.z += bo.z; v1.w += bo.w;
                *(float4*)(C + (size_t)(gr0 + 1) * 40 + col) = v1;
            }
        }
    }
}

// ---------------------------------------------------------------------------
// Pad Wc [128,40] into [128,64] with zeros
// ---------------------------------------------------------------------------
__global__ void pad_wc_k(const float* __restrict__ wc, float* __restrict__ wpad)
{
    int t = blockIdx.x * blockDim.x + threadIdx.x;
    if (t < 128 * 64) {
        int r = t >> 6, c = t & 63;
        wpad[t] = (c < 40) ? wc[r * 40 + c] : 0.f;
    }
}

// ---------------------------------------------------------------------------
// CSR build: counts (self-loop seeded), 3-kernel scan, scatter fill
// ---------------------------------------------------------------------------
__global__ void init_cnt_k(int* __restrict__ cnt, int N)
{
    int i = blockIdx.x * blockDim.x + threadIdx.x;
    if (i < N) cnt[i] = 1;
}

__global__ void count_k(const int* __restrict__ ei, int E, int* __restrict__ cnt)
{
    int i = blockIdx.x * blockDim.x + threadIdx.x;
    if (i < E) atomicAdd(cnt + __ldg(ei + E + i), 1);
}

__global__ void blocksum_k(const int* __restrict__ cnt, int* __restrict__ bsum, int N)
{
    __shared__ int s[256];
    int i = blockIdx.x * 256 + threadIdx.x;
    s[threadIdx.x] = (i < N) ? cnt[i] : 0;
    __syncthreads();
#pragma unroll
    for (int st = 128; st > 0; st >>= 1) {
        if (threadIdx.x < st) s[threadIdx.x] += s[threadIdx.x + st];
        __syncthreads();
    }
    if (threadIdx.x == 0) bsum[blockIdx.x] = s[0];
}

__global__ void scan_bsums_k(int* __restrict__ bsum, int NB)
{
    __shared__ int s[NBMAX];
    int t = threadIdx.x;
    int x = (t < NB) ? bsum[t] : 0;
    s[t] = x;
    __syncthreads();
#pragma unroll
    for (int off = 1; off < NBMAX; off <<= 1) {
        int v = (t >= off) ? s[t - off] : 0;
        __syncthreads();
        s[t] += v;
        __syncthreads();
    }
    bsum[t < NBMAX ? t : 0] = s[t] - x;
}

__global__ void scan_final_k(const int* __restrict__ cnt,
                             const int* __restrict__ boff,
                             int* __restrict__ rowptr,
                             int* __restrict__ wcur, int N)
{
    __shared__ int s[256];
    int t = threadIdx.x;
    int i = blockIdx.x * 256 + t;
    int x = (i < N) ? cnt[i] : 0;
    s[t] = x;
    __syncthreads();
#pragma unroll
    for (int off = 1; off < 256; off <<= 1) {
        int v = (t >= off) ? s[t - off] : 0;
        __syncthreads();
        s[t] += v;
        __syncthreads();
    }
    int excl = s[t] - x + boff[blockIdx.x];
    if (i < N) {
        rowptr[i] = excl;
        wcur[i] = excl;
        if (i == N - 1) rowptr[N] = excl + x;
    }
}

__global__ void fill_k(const int* __restrict__ ei, int E, int N,
                       int* __restrict__ wcur, int* __restrict__ csrc)
{
    int t = blockIdx.x * blockDim.x + threadIdx.x;
    int T = E + N;
    if (t >= T) return;
    int s, d;
    if (t < E) { s = __ldg(ei + t); d = __ldg(ei + E + t); }
    else       { s = t - E; d = s; }
    int pos = atomicAdd(wcur + d, 1);
    csrc[pos] = s;
}

// ---------------------------------------------------------------------------
// Aggregation: warp per dst node, 1-deep software-pipelined gather.
// ---------------------------------------------------------------------------
__global__ void __launch_bounds__(256) agg_k(
    const int* __restrict__ rowptr, const int* __restrict__ csrc,
    const __half* __restrict__ h16,
    const float* __restrict__ a_s, const float* __restrict__ a_d,
    float* __restrict__ out, int N)
{
    int d = (blockIdx.x * blockDim.x + threadIdx.x) >> 5;
    int lane = threadIdx.x & 31;
    if (d >= N) return;

    int beg = __ldg(rowptr + d);
    int end = __ldg(rowptr + d + 1);
    int head = lane >> 3;
    float ed = __ldg(a_d + 4 * (size_t)d + head);

    float4 acc = make_float4(0.f, 0.f, 0.f, 0.f);
    float den = 0.f;

    // prefetch stage (degree >= 1 always: self-loop)
    int s0 = __ldg(csrc + beg);
    float esA = __ldg(a_s + 4 * (size_t)s0 + head);
    uint2 pkA = *(const uint2*)(h16 + (size_t)s0 * 128 + lane * 4);

    for (int e = beg; e < end; e++) {
        float es = esA;
        uint2 pk = pkA;
        if (e + 1 < end) {
            int sn = __ldg(csrc + e + 1);
            esA = __ldg(a_s + 4 * (size_t)sn + head);
            pkA = *(const uint2*)(h16 + (size_t)sn * 128 + lane * 4);
        }
        float t = es + ed;
        t = (t > 0.f) ? t : 0.2f * t;
        float p = __expf(t);
        float2 f0 = __half22float2(*(__half2*)&pk.x);
        float2 f1 = __half22float2(*(__half2*)&pk.y);
        acc.x = fmaf(p, f0.x, acc.x);
        acc.y = fmaf(p, f0.y, acc.y);
        acc.z = fmaf(p, f1.x, acc.z);
        acc.w = fmaf(p, f1.y, acc.w);
        den += p;
    }
    float inv = 1.0f / (den + 1e-16f);
    acc.x *= inv; acc.y *= inv; acc.z *= inv; acc.w *= inv;
    *(float4*)(out + (size_t)d * 128 + lane * 4) = acc;
}

// ---------------------------------------------------------------------------
extern "C" void kernel_launch(void* const* d_in, const int* in_sizes, int n_in,
                              void* d_out, int out_size)
{
    const float* x   = (const float*)d_in[0];
    const int*   ei  = (const int*)  d_in[1];
    const float* W1  = (const float*)d_in[2];
    const float* as1 = (const float*)d_in[3];
    const float* ad1 = (const float*)d_in[4];
    const float* b1  = (const float*)d_in[5];
    const float* W2  = (const float*)d_in[6];
    const float* as2 = (const float*)d_in[7];
    const float* ad2 = (const float*)d_in[8];
    const float* b2  = (const float*)d_in[9];
    const float* Wc  = (const float*)d_in[10];
    const float* bc  = (const float*)d_in[11];
    float* out = (float*)d_out;

    const int N = in_sizes[0] / 128;
    const int E = in_sizes[1] / 2;

    __half* h16;
    float *obuf, *asb, *adb, *wpad;
    int *rowptr, *wcur, *csrc, *bsum;
    cudaGetSymbolAddress((void**)&h16,    g_h16);
    cudaGetSymbolAddress((void**)&obuf,   g_out);
    cudaGetSymbolAddress((void**)&asb,    g_asrc);
    cudaGetSymbolAddress((void**)&adb,    g_adst);
    cudaGetSymbolAddress((void**)&wpad,   g_wpad);
    cudaGetSymbolAddress((void**)&rowptr, g_rowptr);
    cudaGetSymbolAddress((void**)&wcur,   g_wcur);
    cudaGetSymbolAddress((void**)&csrc,   g_csrc);
    cudaGetSymbolAddress((void**)&bsum,   g_bsum);

    const dim3 gMma((N + 127) / 128);
    const dim3 gCls((N + 127) / 128);
    const int  gAttn = (N * 4 + 255) / 256;
    const int  NB = (N + 255) / 256;
    const int  T = E + N;
    const int  gAgg = (N + 7) / 8;

    // ---- CSR build (shared by both layers) ----
    pad_wc_k<<<(128 * 64 + 255) / 256, 256>>>(Wc, wpad);
    init_cnt_k<<<NB, 256>>>(wcur, N);
    count_k<<<(E + 255) / 256, 256>>>(ei, E, wcur);
    blocksum_k<<<NB, 256>>>(wcur, bsum, N);
    scan_bsums_k<<<1, NBMAX>>>(bsum, NB);
    scan_final_k<<<NB, 256>>>(wcur, bsum, rowptr, wcur, N);
    fill_k<<<(T + 255) / 256, 256>>>(ei, E, N, wcur, csrc);

    // ---- layer 1 (tf32 tensor GEMM -> fp16 h) ----
    mma_gemm_k<<<gMma, 256>>>(x, W1, h16, nullptr, N);
    attn16_k<<<gAttn, 256>>>(h16, as1, ad1, asb, adb, N * 4);
    agg_k<<<gAgg, 256>>>(rowptr, csrc, h16, asb, adb, obuf, N);

    // ---- layer 2 (A-load: relu(a + b1)) ----
    mma_gemm_k<<<gMma, 256>>>(obuf, W2, h16, b1, N);
    attn16_k<<<gAttn, 256>>>(h16, as2, ad2, asb, adb, N * 4);
    agg_k<<<gAgg, 256>>>(rowptr, csrc, h16, asb, adb, obuf, N);

    // ---- classifier (exact fp32 FFMA2), +bc, 40 real cols ----
    gemm_cls_k<<<gCls, 256>>>(obuf, wpad, out, b2, bc, N);
}

// round 8
// speedup vs baseline: 3.3770x; 1.2021x over previous
#include <cuda_runtime.h>
#include <cuda_fp16.h>
#include <cstdint>

#define NN 100000
#define FDIM 128
#define EMAX 1700032
#define NBMAX 512

typedef unsigned long long ull;

// Scratch (device globals — allocation-free per harness rules)
__device__ __half g_h16[NN * FDIM];   // fp16 transformed features (messages)
__device__ float g_out[NN * FDIM];    // normalized aggregated output (fp32)
__device__ float g_asrc[NN * 4];
__device__ float g_adst[NN * 4];
__device__ float g_wpad[FDIM * 64];   // Wc zero-padded to 128x64
__device__ int   g_rowptr[NN + 1];
__device__ int   g_wcur[NN];
__device__ int   g_csrc[EMAX];
__device__ int   g_bsum[NBMAX];

// ---------------------------------------------------------------------------
// packed f32x2 helpers (classifier GEMM)
// ---------------------------------------------------------------------------
#define PACK2(out, lo, hi) \
    asm("mov.b64 %0, {%1, %2};" : "=l"(out) : "f"(lo), "f"(hi))
#define UNPK2(lo, hi, in) \
    asm("mov.b64 {%0, %1}, %2;" : "=f"(lo), "=f"(hi) : "l"(in))
#define FMA2(d, a, b, c) \
    asm("fma.rn.f32x2 %0, %1, %2, %3;" : "=l"(d) : "l"(a), "l"(b), "l"(c))

// tf32 helpers (legacy mma.sync path — compiles for plain sm_103)
__device__ __forceinline__ uint32_t f2tf(float f) {
    uint32_t r;
    asm("cvt.rna.tf32.f32 %0, %1;" : "=r"(r) : "f"(f));
    return r;
}
#define MMA_TF32(c, a, b) \
    asm volatile("mma.sync.aligned.m16n8k8.row.col.f32.tf32.tf32.f32 " \
        "{%0,%1,%2,%3}, {%4,%5,%6,%7}, {%8,%9}, {%0,%1,%2,%3};" \
        : "+f"((c)[0]), "+f"((c)[1]), "+f"((c)[2]), "+f"((c)[3]) \
        : "r"((a)[0]), "r"((a)[1]), "r"((a)[2]), "r"((a)[3]), \
          "r"((b)[0]), "r"((b)[1]))

// ---------------------------------------------------------------------------
// TF32 tensor-core layer GEMM with FUSED attention epilogue:
//   h16[M,128] = act(A[M,128]) @ W[128,128]   (act = relu(a+bias_in) if set)
//   a_s[n,h] = h[n] . att_s[h], a_d[n,h] = h[n] . att_d[h]  (from fp32 accs)
// BM=128, BN=128, BK=32, 256 threads (8 warps: 4 along M x 2 along N).
// ---------------------------------------------------------------------------
__global__ void __launch_bounds__(256) mma_gemm_k(
    const float* __restrict__ A, const float* __restrict__ Wg,
    __half* __restrict__ h16,
    float* __restrict__ a_s, float* __restrict__ a_d,
    const float* __restrict__ att_s, const float* __restrict__ att_d,
    const float* __restrict__ bias_in, int M)
{
    __shared__ uint32_t sA[128][36];
    __shared__ uint32_t sW[32][132];
    __shared__ float satt_s[128], satt_d[128];

    const int tid = threadIdx.x;
    const int lane = tid & 31;
    const int w = tid >> 5;
    const int wm = (w & 3) * 32;
    const int wn = (w >> 2) * 64;
    const int r0 = blockIdx.x * 128;

    if (tid < 128) {
        satt_s[tid] = att_s[tid];
        satt_d[tid] = att_d[tid];
    }

    float acc[2][8][4];
#pragma unroll
    for (int tm = 0; tm < 2; tm++)
#pragma unroll
        for (int tn = 0; tn < 8; tn++)
#pragma unroll
            for (int i = 0; i < 4; i++) acc[tm][tn][i] = 0.f;

    for (int kb = 0; kb < 4; kb++) {
#pragma unroll
        for (int i = 0; i < 4; i++) {
            int idx = tid + i * 256;
            int row = idx >> 3;
            int cg = idx & 7;
            int gr = r0 + row;
            float4 v = make_float4(0.f, 0.f, 0.f, 0.f);
            if (gr < M) {
                v = *(const float4*)(A + (size_t)gr * 128 + kb * 32 + cg * 4);
                if (bias_in) {
                    float4 b = *(const float4*)(bias_in + kb * 32 + cg * 4);
                    v.x = fmaxf(v.x + b.x, 0.f);
                    v.y = fmaxf(v.y + b.y, 0.f);
                    v.z = fmaxf(v.z + b.z, 0.f);
                    v.w = fmaxf(v.w + b.w, 0.f);
                }
            }
            uint4 t = make_uint4(f2tf(v.x), f2tf(v.y), f2tf(v.z), f2tf(v.w));
            *(uint4*)&sA[row][cg * 4] = t;
        }
#pragma unroll
        for (int i = 0; i < 4; i++) {
            int idx = tid + i * 256;
            int k = idx >> 5;
            int ng = idx & 31;
            float4 v = *(const float4*)(Wg + (size_t)(kb * 32 + k) * 128 + ng * 4);
            uint4 t = make_uint4(f2tf(v.x), f2tf(v.y), f2tf(v.z), f2tf(v.w));
            *(uint4*)&sW[k][ng * 4] = t;
        }
        __syncthreads();

#pragma unroll
        for (int k8 = 0; k8 < 4; k8++) {
            const int kq = k8 * 8 + (lane & 3);
            const int rb = wm + (lane >> 2);
            const int nb = wn + (lane >> 2);
            uint32_t a[2][4], b[8][2];
#pragma unroll
            for (int tm = 0; tm < 2; tm++) {
                a[tm][0] = sA[rb + tm * 16 + 0][kq];
                a[tm][1] = sA[rb + tm * 16 + 8][kq];
                a[tm][2] = sA[rb + tm * 16 + 0][kq + 4];
                a[tm][3] = sA[rb + tm * 16 + 8][kq + 4];
            }
#pragma unroll
            for (int tn = 0; tn < 8; tn++) {
                b[tn][0] = sW[kq + 0][nb + tn * 8];
                b[tn][1] = sW[kq + 4][nb + tn * 8];
            }
#pragma unroll
            for (int tm = 0; tm < 2; tm++)
#pragma unroll
                for (int tn = 0; tn < 8; tn++)
                    MMA_TF32(acc[tm][tn], a[tm], b[tn]);
        }
        __syncthreads();
    }

    // ---- fused epilogue: fp16 store + attn logits from fp32 accs ----
    const int headA = wn >> 5;   // this warp covers heads headA, headA+1
#pragma unroll
    for (int tm = 0; tm < 2; tm++)
#pragma unroll
        for (int h2 = 0; h2 < 2; h2++) {
            int gr = r0 + wm + tm * 16 + (lane >> 2) + 8 * h2;
            if (gr < M) {
#pragma unroll
                for (int tn = 0; tn < 8; tn++) {
                    __half2 hh = __floats2half2_rn(acc[tm][tn][2 * h2],
                                                   acc[tm][tn][2 * h2 + 1]);
                    *(uint32_t*)(h16 + (size_t)gr * 128 + wn + tn * 8 +
                                 (lane & 3) * 2) = *(uint32_t*)&hh;
                }
            }
            float s0 = 0.f, d0 = 0.f, s1 = 0.f, d1 = 0.f;
#pragma unroll
            for (int tn = 0; tn < 4; tn++) {
                int col = wn + tn * 8 + (lane & 3) * 2;
                float x0 = acc[tm][tn][2 * h2], x1 = acc[tm][tn][2 * h2 + 1];
                s0 += x0 * satt_s[col] + x1 * satt_s[col + 1];
                d0 += x0 * satt_d[col] + x1 * satt_d[col + 1];
            }
#pragma unroll
            for (int tn = 4; tn < 8; tn++) {
                int col = wn + tn * 8 + (lane & 3) * 2;
                float x0 = acc[tm][tn][2 * h2], x1 = acc[tm][tn][2 * h2 + 1];
                s1 += x0 * satt_s[col] + x1 * satt_s[col + 1];
                d1 += x0 * satt_d[col] + x1 * satt_d[col + 1];
            }
#pragma unroll
            for (int off = 1; off <= 2; off <<= 1) {
                s0 += __shfl_xor_sync(0xFFFFFFFF, s0, off);
                d0 += __shfl_xor_sync(0xFFFFFFFF, d0, off);
                s1 += __shfl_xor_sync(0xFFFFFFFF, s1, off);
                d1 += __shfl_xor_sync(0xFFFFFFFF, d1, off);
            }
            if ((lane & 3) == 0 && gr < M) {
                a_s[(size_t)gr * 4 + headA] = s0;
                a_d[(size_t)gr * 4 + headA] = d0;
                a_s[(size_t)gr * 4 + headA + 1] = s1;
                a_d[(size_t)gr * 4 + headA + 1] = d1;
            }
        }
}

// ---------------------------------------------------------------------------
// Classifier GEMM (exact fp32 FFMA2): C[M,40] = relu(A + b_in) @ Wpad[128,64] + b_out
// ---------------------------------------------------------------------------
__global__ void __launch_bounds__(256) gemm_cls_k(
    const float* __restrict__ A, const float* __restrict__ W,
    float* __restrict__ C,
    const float* __restrict__ bias_in, const float* __restrict__ bias_out,
    int M)
{
    __shared__ float sAT[32][130];
    __shared__ float sW[32][64];

    const int tid = threadIdx.x;
    const int tx = tid & 15;
    const int ty = tid >> 4;
    const int r0 = blockIdx.x * 128;

    ull acc[4][4];
#pragma unroll
    for (int p = 0; p < 4; p++)
#pragma unroll
        for (int c = 0; c < 4; c++) acc[p][c] = 0ull;

    for (int k0 = 0; k0 < 128; k0 += 32) {
#pragma unroll
        for (int i = 0; i < 4; i++) {
            int f = tid + i * 256;
            int row = f >> 3;
            int cg = f & 7;
            int grow = r0 + row;
            float4 v = make_float4(0.f, 0.f, 0.f, 0.f);
            if (grow < M) {
                v = *(const float4*)(A + (size_t)grow * 128 + k0 + cg * 4);
                float4 b = *(const float4*)(bias_in + k0 + cg * 4);
                v.x = fmaxf(v.x + b.x, 0.f);
                v.y = fmaxf(v.y + b.y, 0.f);
                v.z = fmaxf(v.z + b.z, 0.f);
                v.w = fmaxf(v.w + b.w, 0.f);
            }
            sAT[cg * 4 + 0][row] = v.x;
            sAT[cg * 4 + 1][row] = v.y;
            sAT[cg * 4 + 2][row] = v.z;
            sAT[cg * 4 + 3][row] = v.w;
        }
#pragma unroll
        for (int i = 0; i < 2; i++) {
            int f = tid + i * 256;
            int row = f >> 4;
            int cg = f & 15;
            *(float4*)&sW[row][cg * 4] =
                *(const float4*)(W + (size_t)(k0 + row) * 64 + cg * 4);
        }
        __syncthreads();

#pragma unroll 8
        for (int k = 0; k < 32; k++) {
            float4 w = *(float4*)&sW[k][tx * 4];
            ull b0, b1, b2, b3;
            PACK2(b0, w.x, w.x);
            PACK2(b1, w.y, w.y);
            PACK2(b2, w.z, w.z);
            PACK2(b3, w.w, w.w);
            const ull* ap = (const ull*)&sAT[k][ty * 8];
            ull a0 = ap[0], a1 = ap[1], a2 = ap[2], a3 = ap[3];
            FMA2(acc[0][0], a0, b0, acc[0][0]);
            FMA2(acc[0][1], a0, b1, acc[0][1]);
            FMA2(acc[0][2], a0, b2, acc[0][2]);
            FMA2(acc[0][3], a0, b3, acc[0][3]);
            FMA2(acc[1][0], a1, b0, acc[1][0]);
            FMA2(acc[1][1], a1, b1, acc[1][1]);
            FMA2(acc[1][2], a1, b2, acc[1][2]);
            FMA2(acc[1][3], a1, b3, acc[1][3]);
            FMA2(acc[2][0], a2, b0, acc[2][0]);
            FMA2(acc[2][1], a2, b1, acc[2][1]);
            FMA2(acc[2][2], a2, b2, acc[2][2]);
            FMA2(acc[2][3], a2, b3, acc[2][3]);
            FMA2(acc[3][0], a3, b0, acc[3][0]);
            FMA2(acc[3][1], a3, b1, acc[3][1]);
            FMA2(acc[3][2], a3, b2, acc[3][2]);
            FMA2(acc[3][3], a3, b3, acc[3][3]);
        }
        __syncthreads();
    }

    int col = tx * 4;
    if (col < 40) {
        float4 bo = *(const float4*)(bias_out + col);
#pragma unroll
        for (int p = 0; p < 4; p++) {
            float4 v0, v1;
            UNPK2(v0.x, v1.x, acc[p][0]);
            UNPK2(v0.y, v1.y, acc[p][1]);
            UNPK2(v0.z, v1.z, acc[p][2]);
            UNPK2(v0.w, v1.w, acc[p][3]);
            int gr0 = r0 + ty * 8 + 2 * p;
            if (gr0 < M) {
                v0.x += bo.x; v0.y += bo.y; v0.z += bo.z; v0.w += bo.w;
                *(float4*)(C + (size_t)gr0 * 40 + col) = v0;
            }
            if (gr0 + 1 < M) {
                v1.x += bo.x; v1.y += bo.y; v1.z += bo.z; v1.w += bo.w;
                *(float4*)(C + (size_t)(gr0 + 1) * 40 + col) = v1;
            }
        }
    }
}

// ---------------------------------------------------------------------------
// prep: pad Wc into [128,64] AND seed counts with self-loop (fused)
// ---------------------------------------------------------------------------
__global__ void prep_k(const float* __restrict__ wc, float* __restrict__ wpad,
                       int* __restrict__ cnt, int N)
{
    int t = blockIdx.x * blockDim.x + threadIdx.x;
    if (t < 128 * 64) {
        int r = t >> 6, c = t & 63;
        wpad[t] = (c < 40) ? wc[r * 40 + c] : 0.f;
    }
    if (t < N) cnt[t] = 1;
}

// ---------------------------------------------------------------------------
// CSR build: count, 3-kernel scan, scatter fill
// ---------------------------------------------------------------------------
__global__ void count_k(const int* __restrict__ ei, int E, int* __restrict__ cnt)
{
    int i = blockIdx.x * blockDim.x + threadIdx.x;
    if (i < E) atomicAdd(cnt + __ldg(ei + E + i), 1);
}

__global__ void blocksum_k(const int* __restrict__ cnt, int* __restrict__ bsum, int N)
{
    __shared__ int s[256];
    int i = blockIdx.x * 256 + threadIdx.x;
    s[threadIdx.x] = (i < N) ? cnt[i] : 0;
    __syncthreads();
#pragma unroll
    for (int st = 128; st > 0; st >>= 1) {
        if (threadIdx.x < st) s[threadIdx.x] += s[threadIdx.x + st];
        __syncthreads();
    }
    if (threadIdx.x == 0) bsum[blockIdx.x] = s[0];
}

__global__ void scan_bsums_k(int* __restrict__ bsum, int NB)
{
    __shared__ int s[NBMAX];
    int t = threadIdx.x;
    int x = (t < NB) ? bsum[t] : 0;
    s[t] = x;
    __syncthreads();
#pragma unroll
    for (int off = 1; off < NBMAX; off <<= 1) {
        int v = (t >= off) ? s[t - off] : 0;
        __syncthreads();
        s[t] += v;
        __syncthreads();
    }
    bsum[t < NBMAX ? t : 0] = s[t] - x;
}

__global__ void scan_final_k(const int* __restrict__ cnt,
                             const int* __restrict__ boff,
                             int* __restrict__ rowptr,
                             int* __restrict__ wcur, int N)
{
    __shared__ int s[256];
    int t = threadIdx.x;
    int i = blockIdx.x * 256 + t;
    int x = (i < N) ? cnt[i] : 0;
    s[t] = x;
    __syncthreads();
#pragma unroll
    for (int off = 1; off < 256; off <<= 1) {
        int v = (t >= off) ? s[t - off] : 0;
        __syncthreads();
        s[t] += v;
        __syncthreads();
    }
    int excl = s[t] - x + boff[blockIdx.x];
    if (i < N) {
        rowptr[i] = excl;
        wcur[i] = excl;
        if (i == N - 1) rowptr[N] = excl + x;
    }
}

__global__ void fill_k(const int* __restrict__ ei, int E, int N,
                       int* __restrict__ wcur, int* __restrict__ csrc)
{
    int t = blockIdx.x * blockDim.x + threadIdx.x;
    int T = E + N;
    if (t >= T) return;
    int s, d;
    if (t < E) { s = __ldg(ei + t); d = __ldg(ei + E + t); }
    else       { s = t - E; d = s; }
    int pos = atomicAdd(wcur + d, 1);
    csrc[pos] = s;
}

// ---------------------------------------------------------------------------
// Aggregation: warp per dst node; TWO edges in flight (half-warps), 16B
// gathers (16 lanes x uint4 = full 128-col row), 1-deep prefetch per half.
// ---------------------------------------------------------------------------
__global__ void __launch_bounds__(256) agg_k(
    const int* __restrict__ rowptr, const int* __restrict__ csrc,
    const __half* __restrict__ h16,
    const float* __restrict__ a_s, const float* __restrict__ a_d,
    float* __restrict__ out, int N)
{
    int d = (blockIdx.x * blockDim.x + threadIdx.x) >> 5;
    int lane = threadIdx.x & 31;
    if (d >= N) return;

    const int half = lane >> 4;
    const int sl = lane & 15;          // cols sl*8 .. sl*8+7
    const int head = sl >> 2;
    int beg = __ldg(rowptr + d);
    int end = __ldg(rowptr + d + 1);
    float ed = __ldg(a_d + 4 * (size_t)d + head);

    float acc[8];
#pragma unroll
    for (int j = 0; j < 8; j++) acc[j] = 0.f;
    float den = 0.f;

    int e = beg + half;
    if (e < end) {
        int s = __ldg(csrc + e);
        float es = __ldg(a_s + 4 * (size_t)s + head);
        uint4 pk = *(const uint4*)(h16 + (size_t)s * 128 + sl * 8);
        for (;;) {
            int e2 = e + 2;
            bool more = e2 < end;
            int sn = 0;
            float esN = 0.f;
            uint4 pkN = make_uint4(0, 0, 0, 0);
            if (more) {
                sn = __ldg(csrc + e2);
                esN = __ldg(a_s + 4 * (size_t)sn + head);
                pkN = *(const uint4*)(h16 + (size_t)sn * 128 + sl * 8);
            }
            float t = es + ed;
            t = (t > 0.f) ? t : 0.2f * t;
            float p = __expf(t);
            den += p;
            const __half2* hp = (const __half2*)&pk;
#pragma unroll
            for (int j = 0; j < 4; j++) {
                float2 f = __half22float2(hp[j]);
                acc[2 * j] = fmaf(p, f.x, acc[2 * j]);
                acc[2 * j + 1] = fmaf(p, f.y, acc[2 * j + 1]);
            }
            if (!more) break;
            e = e2; es = esN; pk = pkN;
        }
    }

    // combine the two halves (all 32 lanes converged here)
#pragma unroll
    for (int j = 0; j < 8; j++)
        acc[j] += __shfl_down_sync(0xFFFFFFFF, acc[j], 16);
    den += __shfl_down_sync(0xFFFFFFFF, den, 16);

    if (half == 0) {
        float inv = 1.0f / (den + 1e-16f);
        float4 v0 = make_float4(acc[0] * inv, acc[1] * inv,
                                acc[2] * inv, acc[3] * inv);
        float4 v1 = make_float4(acc[4] * inv, acc[5] * inv,
                                acc[6] * inv, acc[7] * inv);
        float4* o = (float4*)(out + (size_t)d * 128 + sl * 8);
        o[0] = v0;
        o[1] = v1;
    }
}

// ---------------------------------------------------------------------------
extern "C" void kernel_launch(void* const* d_in, const int* in_sizes, int n_in,
                              void* d_out, int out_size)
{
    const float* x   = (const float*)d_in[0];
    const int*   ei  = (const int*)  d_in[1];
    const float* W1  = (const float*)d_in[2];
    const float* as1 = (const float*)d_in[3];
    const float* ad1 = (const float*)d_in[4];
    const float* b1  = (const float*)d_in[5];
    const float* W2  = (const float*)d_in[6];
    const float* as2 = (const float*)d_in[7];
    const float* ad2 = (const float*)d_in[8];
    const float* b2  = (const float*)d_in[9];
    const float* Wc  = (const float*)d_in[10];
    const float* bc  = (const float*)d_in[11];
    float* out = (float*)d_out;

    const int N = in_sizes[0] / 128;
    const int E = in_sizes[1] / 2;

    __half* h16;
    float *obuf, *asb, *adb, *wpad;
    int *rowptr, *wcur, *csrc, *bsum;
    cudaGetSymbolAddress((void**)&h16,    g_h16);
    cudaGetSymbolAddress((void**)&obuf,   g_out);
    cudaGetSymbolAddress((void**)&asb,    g_asrc);
    cudaGetSymbolAddress((void**)&adb,    g_adst);
    cudaGetSymbolAddress((void**)&wpad,   g_wpad);
    cudaGetSymbolAddress((void**)&rowptr, g_rowptr);
    cudaGetSymbolAddress((void**)&wcur,   g_wcur);
    cudaGetSymbolAddress((void**)&csrc,   g_csrc);
    cudaGetSymbolAddress((void**)&bsum,   g_bsum);

    const dim3 gMma((N + 127) / 128);
    const dim3 gCls((N + 127) / 128);
    const int  NB = (N + 255) / 256;
    const int  T = E + N;
    const int  gAgg = (N + 7) / 8;

    // order chosen so mma_gemm_k is the 4th launch (ncu -s lands there)
    prep_k<<<NB, 256>>>(Wc, wpad, wcur, N);                        // 1
    count_k<<<(E + 255) / 256, 256>>>(ei, E, wcur);                // 2
    blocksum_k<<<NB, 256>>>(wcur, bsum, N);                        // 3
    mma_gemm_k<<<gMma, 256>>>(x, W1, h16, asb, adb, as1, ad1,      // 4
                              nullptr, N);
    scan_bsums_k<<<1, NBMAX>>>(bsum, NB);                          // 5
    scan_final_k<<<NB, 256>>>(wcur, bsum, rowptr, wcur, N);        // 6
    fill_k<<<(T + 255) / 256, 256>>>(ei, E, N, wcur, csrc);        // 7

    agg_k<<<gAgg, 256>>>(rowptr, csrc, h16, asb, adb, obuf, N);    // 8

    mma_gemm_k<<<gMma, 256>>>(obuf, W2, h16, asb, adb, as2, ad2,   // 9
                              b1, N);
    agg_k<<<gAgg, 256>>>(rowptr, csrc, h16, asb, adb, obuf, N);    // 10

    gemm_cls_k<<<gCls, 256>>>(obuf, wpad, out, b2, bc, N);         // 11
}